// round 2
// baseline (speedup 1.0000x reference)
#include <cuda_runtime.h>
#include <cuda_bf16.h>
#include <cstdint>

// Problem constants (fixed by the dataset)
#define B_ROWS   8192
#define D_IN     768
#define D_LAT    16384
#define K_TOP    32

// ---------------------------------------------------------------------------
// Scratch: transposed decoder weights WdT[l][d] = W_dec[d][l]  (50 MB)
// Fallback scratch in case out layout differs from expectation.
// ---------------------------------------------------------------------------
__device__ float g_WdT[(size_t)D_LAT * D_IN];
__device__ float g_z_scratch[(size_t)B_ROWS * D_LAT];
__device__ float g_xhat_scratch[(size_t)B_ROWS * D_IN];

// ---------------------------------------------------------------------------
// K0: transpose W_dec [768, 16384] -> WdT [16384, 768]
// ---------------------------------------------------------------------------
__global__ void transpose_wdec_kernel(const float* __restrict__ in,
                                      float* __restrict__ out) {
    __shared__ float tile[32][33];
    int x = blockIdx.x * 32 + threadIdx.x;   // latent index
    int y = blockIdx.y * 32 + threadIdx.y;   // d index
#pragma unroll
    for (int j = 0; j < 32; j += 8)
        tile[threadIdx.y + j][threadIdx.x] = in[(size_t)(y + j) * D_LAT + x];
    __syncthreads();
    int xo = blockIdx.y * 32 + threadIdx.x;  // d
    int yo = blockIdx.x * 32 + threadIdx.y;  // latent
#pragma unroll
    for (int j = 0; j < 32; j += 8)
        out[(size_t)(yo + j) * D_IN + xo] = tile[threadIdx.x][threadIdx.y + j];
}

// ---------------------------------------------------------------------------
// K1: z = relu(x @ W_enc^T)   fp32 SGEMM, TN layout (both K-contiguous)
//     A = x [8192, 768], B = W_enc [16384, 768], C = z [8192, 16384]
//     128x128 tile, BK=8, 256 threads, 8x8 micro-tile (split 4+4 quadrants)
// ---------------------------------------------------------------------------
__global__ __launch_bounds__(256) void sgemm_relu_kernel(
    const float* __restrict__ A, const float* __restrict__ B,
    float* __restrict__ C) {
    const int BM = 128, BN = 128, BK = 8;
    __shared__ float As[BK][BM];
    __shared__ float Bs[BK][BN];

    int tid = threadIdx.x;
    int bm = blockIdx.y * BM;
    int bn = blockIdx.x * BN;

    int lr = tid >> 1;            // 0..127 (tile row to load)
    int lc = (tid & 1) * 4;       // 0 or 4 (k offset)
    const float* Arow = A + (size_t)(bm + lr) * D_IN + lc;
    const float* Brow = B + (size_t)(bn + lr) * D_IN + lc;

    int tx = (tid & 15) * 4;      // col base in [0,64)
    int ty = (tid >> 4) * 4;      // row base in [0,64)

    float acc[8][8];
#pragma unroll
    for (int i = 0; i < 8; i++)
#pragma unroll
        for (int j = 0; j < 8; j++) acc[i][j] = 0.0f;

    for (int k0 = 0; k0 < D_IN; k0 += BK) {
        float4 a4 = *reinterpret_cast<const float4*>(Arow + k0);
        float4 b4 = *reinterpret_cast<const float4*>(Brow + k0);
        As[lc + 0][lr] = a4.x; As[lc + 1][lr] = a4.y;
        As[lc + 2][lr] = a4.z; As[lc + 3][lr] = a4.w;
        Bs[lc + 0][lr] = b4.x; Bs[lc + 1][lr] = b4.y;
        Bs[lc + 2][lr] = b4.z; Bs[lc + 3][lr] = b4.w;
        __syncthreads();
#pragma unroll
        for (int kk = 0; kk < BK; kk++) {
            float ar[8], br[8];
            *reinterpret_cast<float4*>(&ar[0]) =
                *reinterpret_cast<const float4*>(&As[kk][ty]);
            *reinterpret_cast<float4*>(&ar[4]) =
                *reinterpret_cast<const float4*>(&As[kk][ty + 64]);
            *reinterpret_cast<float4*>(&br[0]) =
                *reinterpret_cast<const float4*>(&Bs[kk][tx]);
            *reinterpret_cast<float4*>(&br[4]) =
                *reinterpret_cast<const float4*>(&Bs[kk][tx + 64]);
#pragma unroll
            for (int i = 0; i < 8; i++)
#pragma unroll
                for (int j = 0; j < 8; j++) acc[i][j] += ar[i] * br[j];
        }
        __syncthreads();
    }

    // Epilogue: ReLU + store
#pragma unroll
    for (int i = 0; i < 8; i++) {
        int m = bm + ((i < 4) ? (ty + i) : (60 + ty + i));  // 64+ty+(i-4)
        float* Crow = C + (size_t)m * D_LAT + bn;
        float4 v0, v1;
        v0.x = fmaxf(acc[i][0], 0.0f); v0.y = fmaxf(acc[i][1], 0.0f);
        v0.z = fmaxf(acc[i][2], 0.0f); v0.w = fmaxf(acc[i][3], 0.0f);
        v1.x = fmaxf(acc[i][4], 0.0f); v1.y = fmaxf(acc[i][5], 0.0f);
        v1.z = fmaxf(acc[i][6], 0.0f); v1.w = fmaxf(acc[i][7], 0.0f);
        *reinterpret_cast<float4*>(Crow + tx)      = v0;
        *reinterpret_cast<float4*>(Crow + tx + 64) = v1;
    }
}

// ---------------------------------------------------------------------------
// K2: per-row exact top-32 (radix select over f32 bit patterns; relu => >=0),
//     sparse rewrite of z in place, fused sparse decode x_hat = z_sel @ WdT.
//     One block (256 threads) per batch row; row cached in 64 KB dyn smem.
//     Tie-break: lowest index first (matches jax.lax.top_k).
// ---------------------------------------------------------------------------
#define EQ_CAP 256

__global__ __launch_bounds__(256) void topk_decode_kernel(
    float* __restrict__ z, const float* __restrict__ WdT,
    float* __restrict__ xhat) {
    extern __shared__ float row[];                 // D_LAT floats
    __shared__ int   hist[256];
    __shared__ int   s_prefix, s_remaining, s_cnt, s_eqcnt, s_poscount;
    __shared__ int   sel_idx[K_TOP];
    __shared__ float sel_val[K_TOP];
    __shared__ int   eq_idx[EQ_CAP];

    int b = blockIdx.x;
    int tid = threadIdx.x;
    float* zrow = z + (size_t)b * D_LAT;

    if (tid == 0) { s_poscount = 0; s_cnt = 0; s_eqcnt = 0; }
    __syncthreads();

    int pos = 0;
    for (int j = tid; j < D_LAT; j += 256) {
        float v = zrow[j];
        row[j] = v;
        if (v > 0.0f) pos++;
    }
    atomicAdd(&s_poscount, pos);
    __syncthreads();

    bool do_radix = (s_poscount >= K_TOP);
    if (tid == 0) {
        s_prefix = 0;
        s_remaining = do_radix ? K_TOP : (K_TOP - s_poscount);
    }
    __syncthreads();

    if (do_radix) {
        for (int level = 0; level < 4; level++) {
            int shift = 24 - 8 * level;
            hist[tid] = 0;
            __syncthreads();
            int prefix = s_prefix;
            for (int j = tid; j < D_LAT; j += 256) {
                float v = row[j];
                if (v <= 0.0f) continue;
                unsigned u = __float_as_uint(v);
                if (level == 0 || (int)(u >> (32 - 8 * level)) == prefix)
                    atomicAdd(&hist[(u >> shift) & 255], 1);
            }
            __syncthreads();
            if (tid == 0) {
                int rem = s_remaining;
                int cum = 0, d = 255;
                for (; d >= 0; d--) {
                    int h = hist[d];
                    if (cum + h >= rem) break;
                    cum += h;
                }
                s_remaining = rem - cum;            // >= 1
                s_prefix = (prefix << 8) | d;
            }
            __syncthreads();
        }
    }
    unsigned Tbits = do_radix ? (unsigned)s_prefix : 0u;
    float Tval = __uint_as_float(Tbits);
    int remaining = s_remaining;                    // # to take from == T

    // Selection pass: keep strictly-greater, zero everything else for now.
    for (int j = tid; j < D_LAT; j += 256) {
        float v = row[j];
        unsigned u = __float_as_uint(v);
        bool gt = (v > 0.0f) && (u > Tbits);
        zrow[j] = gt ? v : 0.0f;
        if (gt) {
            int p = atomicAdd(&s_cnt, 1);
            sel_idx[p] = j; sel_val[p] = v;
        } else if (u == Tbits) {
            int p = atomicAdd(&s_eqcnt, 1);
            if (p < EQ_CAP) eq_idx[p] = j;
        }
    }
    __syncthreads();

    // Resolve ties: take the `remaining` equal-valued entries with the
    // SMALLEST indices (jax top_k stability).
    if (tid == 0) {
        int base = s_cnt;                           // == K_TOP - remaining
        if (s_eqcnt <= EQ_CAP) {
            int n = s_eqcnt;
            for (int i = 1; i < n; i++) {           // insertion sort (tiny n)
                int key = eq_idx[i], p = i - 1;
                while (p >= 0 && eq_idx[p] > key) { eq_idx[p + 1] = eq_idx[p]; p--; }
                eq_idx[p + 1] = key;
            }
            for (int i = 0; i < remaining; i++) {
                int j = eq_idx[i];
                zrow[j] = Tval;
                sel_idx[base + i] = j; sel_val[base + i] = Tval;
            }
        } else {                                    // pathological fallback
            int got = 0;
            for (int j = 0; j < D_LAT && got < remaining; j++) {
                if (__float_as_uint(row[j]) == Tbits) {
                    zrow[j] = Tval;
                    sel_idx[base + got] = j; sel_val[base + got] = Tval;
                    got++;
                }
            }
        }
    }
    __syncthreads();

    // Fused sparse decode: x_hat[b,d] = sum_i sel_val[i] * WdT[sel_idx[i]*768+d]
    for (int d0 = tid; d0 < D_IN; d0 += 256) {
        float acc = 0.0f;
#pragma unroll
        for (int i = 0; i < K_TOP; i++)
            acc = fmaf(sel_val[i], WdT[(size_t)sel_idx[i] * D_IN + d0], acc);
        xhat[(size_t)b * D_IN + d0] = acc;
    }
}

// ---------------------------------------------------------------------------
// Launch
// ---------------------------------------------------------------------------
extern "C" void kernel_launch(void* const* d_in, const int* in_sizes, int n_in,
                              void* d_out, int out_size) {
    const float* x     = (const float*)d_in[0];
    const float* W_enc = (const float*)d_in[1];
    const float* W_dec = (const float*)d_in[2];
    (void)in_sizes; (void)n_in;

    float* out = (float*)d_out;
    const size_t xhat_elems = (size_t)B_ROWS * D_IN;
    const size_t z_elems    = (size_t)B_ROWS * D_LAT;

    float *xhat, *zout;
    if ((size_t)out_size >= xhat_elems + z_elems) {
        xhat = out;                 // tuple order (x_hat, z) concatenated
        zout = out + xhat_elems;
    } else if ((size_t)out_size == z_elems) {
        zout = out;
        cudaGetSymbolAddress((void**)&xhat, g_xhat_scratch);
    } else {
        xhat = out;
        cudaGetSymbolAddress((void**)&zout, g_z_scratch);
    }

    float* WdT;
    cudaGetSymbolAddress((void**)&WdT, g_WdT);

    // K0: transpose decoder weights
    dim3 tgrid(D_LAT / 32, D_IN / 32), tblk(32, 8);
    transpose_wdec_kernel<<<tgrid, tblk>>>(W_dec, WdT);

    // K1: encoder GEMM + ReLU (dense z written into output z region as scratch)
    dim3 ggrid(D_LAT / 128, B_ROWS / 128);
    sgemm_relu_kernel<<<ggrid, 256>>>(x, W_enc, zout);

    // K2: exact top-32 + sparse rewrite + fused decode
    static bool attr_set = false;
    (void)attr_set; // attribute set is idempotent; call every time (cheap, capture-legal)
    cudaFuncSetAttribute(topk_decode_kernel,
                         cudaFuncAttributeMaxDynamicSharedMemorySize,
                         D_LAT * sizeof(float));
    topk_decode_kernel<<<B_ROWS, 256, D_LAT * sizeof(float)>>>(zout, WdT, xhat);
}

// round 8
// speedup vs baseline: 1.3119x; 1.3119x over previous
#include <cuda_runtime.h>
#include <cuda_bf16.h>
#include <cstdint>

#define B_ROWS   8192
#define D_IN     768
#define D_LAT    16384
#define K_TOP    32

// ---------------------------------------------------------------------------
// Helpers
// ---------------------------------------------------------------------------
__device__ __forceinline__ uint32_t smem_to_u32(const void* p) {
    uint32_t a;
    asm("{ .reg .u64 t; cvta.to.shared.u64 t, %1; cvt.u32.u64 %0, t; }"
        : "=r"(a) : "l"(p));
    return a;
}
__device__ __forceinline__ void cp16(uint32_t dst, const void* src) {
    asm volatile("cp.async.cg.shared.global [%0], [%1], 16;" :: "r"(dst), "l"(src));
}
#define CP_COMMIT() asm volatile("cp.async.commit_group;" ::: "memory")
#define CP_WAIT(n)  asm volatile("cp.async.wait_group %0;" :: "n"(n) : "memory")

// ---------------------------------------------------------------------------
// Device scratch
// ---------------------------------------------------------------------------
__device__ __nv_bfloat16 g_xb[(size_t)B_ROWS * D_IN];
__device__ __nv_bfloat16 g_web[(size_t)D_LAT * D_IN];
__device__ __nv_bfloat16 g_zb[(size_t)B_ROWS * D_LAT];
__device__ float         g_WdT[(size_t)D_LAT * D_IN];

// ---------------------------------------------------------------------------
// K0a: fp32 -> bf16 convert
// ---------------------------------------------------------------------------
__global__ void sae_cvt_bf16(const float* __restrict__ in,
                             __nv_bfloat16* __restrict__ out, int n4) {
    for (int i = blockIdx.x * blockDim.x + threadIdx.x; i < n4;
         i += gridDim.x * blockDim.x) {
        float4 v = reinterpret_cast<const float4*>(in)[i];
        __nv_bfloat162* o = reinterpret_cast<__nv_bfloat162*>(out) + 2 * (size_t)i;
        o[0] = __floats2bfloat162_rn(v.x, v.y);
        o[1] = __floats2bfloat162_rn(v.z, v.w);
    }
}

// ---------------------------------------------------------------------------
// K0b: transpose W_dec [768, 16384] -> WdT [16384, 768]
// ---------------------------------------------------------------------------
__global__ void sae_transpose_wdec(const float* __restrict__ in,
                                   float* __restrict__ out) {
    __shared__ float tile[32][33];
    int x = blockIdx.x * 32 + threadIdx.x;
    int y = blockIdx.y * 32 + threadIdx.y;
#pragma unroll
    for (int j = 0; j < 32; j += 8)
        tile[threadIdx.y + j][threadIdx.x] = in[(size_t)(y + j) * D_LAT + x];
    __syncthreads();
    int xo = blockIdx.y * 32 + threadIdx.x;
    int yo = blockIdx.x * 32 + threadIdx.y;
#pragma unroll
    for (int j = 0; j < 32; j += 8)
        out[(size_t)(yo + j) * D_IN + xo] = tile[threadIdx.x][threadIdx.y + j];
}

// ---------------------------------------------------------------------------
// K1: mma.sync bf16 GEMM.  zb = relu(x @ W_enc^T) (bf16 out).
//     128x128 tile, BK=64, XOR swizzle, 8 warps (2x4), warp tile 64x32,
//     double-buffered cp.async.
// ---------------------------------------------------------------------------
#define BM 128
#define BN 128
#define BK 64
#define NKT (D_IN / BK)
#define TILE_BYTES (128 * 128)
#define GEMM_SMEM (2 * 2 * TILE_BYTES)

__device__ __forceinline__ void ldm_x4(uint32_t* r, uint32_t addr) {
    asm volatile("ldmatrix.sync.aligned.m8n8.x4.shared.b16 {%0,%1,%2,%3}, [%4];"
                 : "=r"(r[0]), "=r"(r[1]), "=r"(r[2]), "=r"(r[3]) : "r"(addr));
}
__device__ __forceinline__ void ldm_x2(uint32_t* r, uint32_t addr) {
    asm volatile("ldmatrix.sync.aligned.m8n8.x2.shared.b16 {%0,%1}, [%2];"
                 : "=r"(r[0]), "=r"(r[1]) : "r"(addr));
}
__device__ __forceinline__ void mma16816(float* c, const uint32_t* a,
                                         const uint32_t* b) {
    asm volatile(
        "mma.sync.aligned.m16n8k16.row.col.f32.bf16.bf16.f32 "
        "{%0,%1,%2,%3}, {%4,%5,%6,%7}, {%8,%9}, {%0,%1,%2,%3};"
        : "+f"(c[0]), "+f"(c[1]), "+f"(c[2]), "+f"(c[3])
        : "r"(a[0]), "r"(a[1]), "r"(a[2]), "r"(a[3]), "r"(b[0]), "r"(b[1]));
}

__device__ __forceinline__ void load_stage(const __nv_bfloat16* __restrict__ A,
                                           const __nv_bfloat16* __restrict__ B,
                                           int bm, int bn, int kt,
                                           uint32_t sA, uint32_t sB, int tid) {
    int r = tid & 127;
    const char* g;
    uint32_t base;
    if (tid < 128) {
        g = (const char*)(A + (size_t)(bm + r) * D_IN + kt * BK);
        base = sA + r * 128;
    } else {
        g = (const char*)(B + (size_t)(bn + r) * D_IN + kt * BK);
        base = sB + r * 128;
    }
    uint32_t xw = (r & 7) << 4;
#pragma unroll
    for (int j = 0; j < 8; j++) cp16(base + ((j * 16) ^ xw), g + j * 16);
}

__global__ __launch_bounds__(256) void sae_gemm_mma(
    const __nv_bfloat16* __restrict__ A,
    const __nv_bfloat16* __restrict__ B,
    __nv_bfloat16* __restrict__ zb) {
    extern __shared__ char smem[];
    uint32_t sb = smem_to_u32(smem);
    uint32_t sA[2] = { sb, sb + TILE_BYTES };
    uint32_t sB[2] = { sb + 2 * TILE_BYTES, sb + 3 * TILE_BYTES };

    int tid = threadIdx.x, wid = tid >> 5, lane = tid & 31;
    int wm = wid >> 2, wn = wid & 3;
    int bm = blockIdx.y * BM, bn = blockIdx.x * BN;

    float acc[4][4][4];
#pragma unroll
    for (int mi = 0; mi < 4; mi++)
#pragma unroll
        for (int ni = 0; ni < 4; ni++)
#pragma unroll
            for (int q = 0; q < 4; q++) acc[mi][ni][q] = 0.0f;

    load_stage(A, B, bm, bn, 0, sA[0], sB[0], tid); CP_COMMIT();
    load_stage(A, B, bm, bn, 1, sA[1], sB[1], tid); CP_COMMIT();

    for (int kt = 0; kt < NKT; kt++) {
        if (kt == NKT - 1) { CP_WAIT(0); } else { CP_WAIT(1); }
        __syncthreads();
        uint32_t cA = sA[kt & 1], cB = sB[kt & 1];

#pragma unroll
        for (int ks = 0; ks < 4; ks++) {
            uint32_t af[4][4], bf[4][2];
#pragma unroll
            for (int mi = 0; mi < 4; mi++) {
                int r = wm * 64 + mi * 16 + (lane & 15);
                uint32_t off = (uint32_t)(ks * 32 + ((lane >> 4) * 16));
                ldm_x4(af[mi], cA + r * 128 + (off ^ ((r & 7) << 4)));
            }
#pragma unroll
            for (int ni = 0; ni < 4; ni++) {
                int n = wn * 32 + ni * 8 + (lane & 7);
                uint32_t off = (uint32_t)(ks * 32 + (((lane >> 3) & 1) * 16));
                ldm_x2(bf[ni], cB + n * 128 + (off ^ ((n & 7) << 4)));
            }
#pragma unroll
            for (int mi = 0; mi < 4; mi++)
#pragma unroll
                for (int ni = 0; ni < 4; ni++)
                    mma16816(acc[mi][ni], af[mi], bf[ni]);
        }
        __syncthreads();
        if (kt + 2 < NKT) {
            load_stage(A, B, bm, bn, kt + 2, sA[kt & 1], sB[kt & 1], tid);
            CP_COMMIT();
        }
    }

    int row_base = bm + wm * 64 + (lane >> 2);
    int col_base = bn + wn * 32 + (lane & 3) * 2;
#pragma unroll
    for (int mi = 0; mi < 4; mi++) {
#pragma unroll
        for (int ni = 0; ni < 4; ni++) {
            int col = col_base + ni * 8;
            float* c = acc[mi][ni];
            __nv_bfloat162 v01 = __floats2bfloat162_rn(fmaxf(c[0], 0.f), fmaxf(c[1], 0.f));
            __nv_bfloat162 v23 = __floats2bfloat162_rn(fmaxf(c[2], 0.f), fmaxf(c[3], 0.f));
            int r0 = row_base + mi * 16;
            *reinterpret_cast<__nv_bfloat162*>(zb + (size_t)r0 * D_LAT + col) = v01;
            *reinterpret_cast<__nv_bfloat162*>(zb + (size_t)(r0 + 8) * D_LAT + col) = v23;
        }
    }
}

// ---------------------------------------------------------------------------
// K2: per row — approx top-96 candidates (16-bit radix on bf16 bits),
//     exact fp32 recompute with sequential k-order (reference-matching
//     rounding), exact top-32 (idx tie-break), z write + fused decode.
// ---------------------------------------------------------------------------
#define NCAND_T 96
#define CAND_CAP 256

__global__ __launch_bounds__(256) void sae_topk_exact(
    const __nv_bfloat16* __restrict__ zb,
    const float* __restrict__ x, const float* __restrict__ W_enc,
    const float* __restrict__ WdT,
    float* __restrict__ zout, float* __restrict__ xhat) {
    __shared__ unsigned short row16[D_LAT];
    __shared__ float xrow[D_IN];
    __shared__ int hist[256];
    __shared__ int s_pos, s_ncand, s_prefix, s_rem, s_nsel;
    __shared__ int   cidx[CAND_CAP];
    __shared__ float cval[CAND_CAP];
    __shared__ int   sel_idx[K_TOP];
    __shared__ float sel_val[K_TOP];

    int b = blockIdx.x, tid = threadIdx.x;
    int wid = tid >> 5, lane = tid & 31;

    const uint4* src = reinterpret_cast<const uint4*>(zb + (size_t)b * D_LAT);
    for (int i = tid; i < D_LAT / 8; i += 256)
        reinterpret_cast<uint4*>(row16)[i] = src[i];
    for (int i = tid; i < D_IN; i += 256) xrow[i] = x[(size_t)b * D_IN + i];
    if (tid == 0) { s_pos = 0; s_ncand = 0; }
    if (tid < K_TOP) { sel_val[tid] = 0.0f; sel_idx[tid] = 0; }
    hist[tid] = 0;
    __syncthreads();

    int cnt = 0;
    for (int j = tid; j < D_LAT; j += 256) {
        unsigned u = row16[j];
        if (u && !(u & 0x8000)) { cnt++; atomicAdd(&hist[u >> 8], 1); }
    }
    atomicAdd(&s_pos, cnt);
    __syncthreads();

    unsigned T16 = 0;
    if (s_pos >= NCAND_T) {
        if (tid == 0) {
            int cum = 0, d = 255;
            for (; d >= 0; d--) { int h = hist[d]; if (cum + h >= NCAND_T) break; cum += h; }
            s_prefix = d; s_rem = NCAND_T - cum;
        }
        __syncthreads();
        int pfx = s_prefix;
        hist[tid] = 0;
        __syncthreads();
        for (int j = tid; j < D_LAT; j += 256) {
            unsigned u = row16[j];
            if (u && !(u & 0x8000) && (int)(u >> 8) == pfx) atomicAdd(&hist[u & 255], 1);
        }
        __syncthreads();
        if (tid == 0) {
            int cum = 0, d = 255, rem = s_rem;
            for (; d >= 0; d--) { int h = hist[d]; if (cum + h >= rem) break; cum += h; }
            s_prefix = (pfx << 8) | d;
        }
        __syncthreads();
        T16 = (unsigned)s_prefix;
    } else {
        __syncthreads();
    }

    for (int j = tid; j < D_LAT; j += 256) {
        unsigned u = row16[j];
        if (u && !(u & 0x8000) && u >= T16) {
            int p = atomicAdd(&s_ncand, 1);
            if (p < CAND_CAP) cidx[p] = j;
        }
    }
    __syncthreads();
    int ncand = min(s_ncand, CAND_CAP);

    // Exact fp32 recompute: one thread per candidate, single accumulator,
    // sequential k = 0..767 — reproduces the R1 fp32 kernel's rounding
    // pattern, which matched reference selection exactly.
    if (tid < ncand) {
        const float* wr = W_enc + (size_t)cidx[tid] * D_IN;
        float acc = 0.0f;
#pragma unroll 8
        for (int t = 0; t < D_IN; t++) acc = fmaf(xrow[t], wr[t], acc);
        cval[tid] = fmaxf(acc, 0.0f);
    }
    if (tid == 0) s_nsel = min(K_TOP, ncand);
    __syncthreads();

    // exact top-32 with (value desc, index asc) by warp 0
    if (wid == 0) {
        int nsel = s_nsel;
        for (int it = 0; it < nsel; it++) {
            float bv = -1.0f; int bi = 0x7FFFFFFF;
            for (int i = lane; i < ncand; i += 32) {
                float v = cval[i]; int ix = cidx[i];
                if (v > bv || (v == bv && ix < bi)) { bv = v; bi = ix; }
            }
#pragma unroll
            for (int o = 16; o; o >>= 1) {
                float ov = __shfl_xor_sync(0xFFFFFFFF, bv, o);
                int   oi = __shfl_xor_sync(0xFFFFFFFF, bi, o);
                if (ov > bv || (ov == bv && oi < bi)) { bv = ov; bi = oi; }
            }
            if (lane == 0) { sel_val[it] = bv; sel_idx[it] = bi; }
            int win = __shfl_sync(0xFFFFFFFF, bi, 0);
            for (int i = lane; i < ncand; i += 32)
                if (cidx[i] == win) cval[i] = -2.0f;
            __syncwarp();
        }
    }
    __syncthreads();

    float* zr = zout + (size_t)b * D_LAT;
    float4 z4 = make_float4(0.f, 0.f, 0.f, 0.f);
    for (int i = tid; i < D_LAT / 4; i += 256)
        reinterpret_cast<float4*>(zr)[i] = z4;
    __syncthreads();
    if (tid < K_TOP && sel_val[tid] > 0.0f) zr[sel_idx[tid]] = sel_val[tid];

    for (int d = tid; d < D_IN; d += 256) {
        float acc = 0.0f;
#pragma unroll
        for (int i = 0; i < K_TOP; i++)
            acc = fmaf(sel_val[i], WdT[(size_t)sel_idx[i] * D_IN + d], acc);
        xhat[(size_t)b * D_IN + d] = acc;
    }
}

// ---------------------------------------------------------------------------
// Launch
// ---------------------------------------------------------------------------
extern "C" void kernel_launch(void* const* d_in, const int* in_sizes, int n_in,
                              void* d_out, int out_size) {
    const float* x     = (const float*)d_in[0];
    const float* W_enc = (const float*)d_in[1];
    const float* W_dec = (const float*)d_in[2];
    (void)in_sizes; (void)n_in; (void)out_size;

    float* out = (float*)d_out;
    const size_t xhat_elems = (size_t)B_ROWS * D_IN;
    float* xhat = out;
    float* zout = out + xhat_elems;

    __nv_bfloat16 *xb, *web, *zbp; float* WdT;
    cudaGetSymbolAddress((void**)&xb,  g_xb);
    cudaGetSymbolAddress((void**)&web, g_web);
    cudaGetSymbolAddress((void**)&zbp, g_zb);
    cudaGetSymbolAddress((void**)&WdT, g_WdT);

    {
        int n4 = (B_ROWS * D_IN) / 4;
        sae_cvt_bf16<<<(n4 + 255) / 256, 256>>>(x, xb, n4);
        n4 = (D_LAT * D_IN) / 4;
        sae_cvt_bf16<<<(n4 + 255) / 256, 256>>>(W_enc, web, n4);
        dim3 tg(D_LAT / 32, D_IN / 32), tb(32, 8);
        sae_transpose_wdec<<<tg, tb>>>(W_dec, WdT);
    }

    cudaFuncSetAttribute(sae_gemm_mma,
                         cudaFuncAttributeMaxDynamicSharedMemorySize, GEMM_SMEM);
    dim3 gg(D_LAT / BN, B_ROWS / BM);
    sae_gemm_mma<<<gg, 256, GEMM_SMEM>>>(xb, web, zbp);

    sae_topk_exact<<<B_ROWS, 256>>>(zbp, x, W_enc, WdT, zout, xhat);
}

// round 9
// speedup vs baseline: 1.3326x; 1.0158x over previous
#include <cuda_runtime.h>
#include <cuda_bf16.h>
#include <cstdint>

#define B_ROWS   8192
#define D_IN     768
#define D_LAT    16384
#define K_TOP    32

// ---------------------------------------------------------------------------
// Helpers
// ---------------------------------------------------------------------------
__device__ __forceinline__ uint32_t smem_to_u32(const void* p) {
    uint32_t a;
    asm("{ .reg .u64 t; cvta.to.shared.u64 t, %1; cvt.u32.u64 %0, t; }"
        : "=r"(a) : "l"(p));
    return a;
}
__device__ __forceinline__ void cp16(uint32_t dst, const void* src) {
    asm volatile("cp.async.cg.shared.global [%0], [%1], 16;" :: "r"(dst), "l"(src));
}
#define CP_COMMIT() asm volatile("cp.async.commit_group;" ::: "memory")
#define CP_WAIT(n)  asm volatile("cp.async.wait_group %0;" :: "n"(n) : "memory")

// ---------------------------------------------------------------------------
// Device scratch
// ---------------------------------------------------------------------------
__device__ __nv_bfloat16 g_xb[(size_t)B_ROWS * D_IN];
__device__ __nv_bfloat16 g_web[(size_t)D_LAT * D_IN];
__device__ __nv_bfloat16 g_zb[(size_t)B_ROWS * D_LAT];
__device__ float         g_WdT[(size_t)D_LAT * D_IN];

// ---------------------------------------------------------------------------
// K0a: fp32 -> bf16 convert
// ---------------------------------------------------------------------------
__global__ void sae_cvt_bf16(const float* __restrict__ in,
                             __nv_bfloat16* __restrict__ out, int n4) {
    for (int i = blockIdx.x * blockDim.x + threadIdx.x; i < n4;
         i += gridDim.x * blockDim.x) {
        float4 v = reinterpret_cast<const float4*>(in)[i];
        __nv_bfloat162* o = reinterpret_cast<__nv_bfloat162*>(out) + 2 * (size_t)i;
        o[0] = __floats2bfloat162_rn(v.x, v.y);
        o[1] = __floats2bfloat162_rn(v.z, v.w);
    }
}

// ---------------------------------------------------------------------------
// K0b: transpose W_dec [768, 16384] -> WdT [16384, 768]
// ---------------------------------------------------------------------------
__global__ void sae_transpose_wdec(const float* __restrict__ in,
                                   float* __restrict__ out) {
    __shared__ float tile[32][33];
    int x = blockIdx.x * 32 + threadIdx.x;
    int y = blockIdx.y * 32 + threadIdx.y;
#pragma unroll
    for (int j = 0; j < 32; j += 8)
        tile[threadIdx.y + j][threadIdx.x] = in[(size_t)(y + j) * D_LAT + x];
    __syncthreads();
    int xo = blockIdx.y * 32 + threadIdx.x;
    int yo = blockIdx.x * 32 + threadIdx.y;
#pragma unroll
    for (int j = 0; j < 32; j += 8)
        out[(size_t)(yo + j) * D_IN + xo] = tile[threadIdx.x][threadIdx.y + j];
}

// ---------------------------------------------------------------------------
// K1: mma.sync bf16 GEMM.  zb = relu(x @ W_enc^T) (bf16 out).
//     128x128 tile, BK=64, XOR swizzle, 8 warps (2x4), warp tile 64x32,
//     3-stage cp.async pipeline, ONE __syncthreads per k-iter.
// ---------------------------------------------------------------------------
#define BM 128
#define BN 128
#define BK 64
#define NKT (D_IN / BK)                   // 12
#define TILE_BYTES (128 * 128)            // 16 KB per operand tile
#define NSTAGE 3
#define STAGE_BYTES (2 * TILE_BYTES)      // 32 KB (A + B)
#define GEMM_SMEM (NSTAGE * STAGE_BYTES)  // 96 KB

__device__ __forceinline__ void ldm_x4(uint32_t* r, uint32_t addr) {
    asm volatile("ldmatrix.sync.aligned.m8n8.x4.shared.b16 {%0,%1,%2,%3}, [%4];"
                 : "=r"(r[0]), "=r"(r[1]), "=r"(r[2]), "=r"(r[3]) : "r"(addr));
}
__device__ __forceinline__ void ldm_x2(uint32_t* r, uint32_t addr) {
    asm volatile("ldmatrix.sync.aligned.m8n8.x2.shared.b16 {%0,%1}, [%2];"
                 : "=r"(r[0]), "=r"(r[1]) : "r"(addr));
}
__device__ __forceinline__ void mma16816(float* c, const uint32_t* a,
                                         const uint32_t* b) {
    asm volatile(
        "mma.sync.aligned.m16n8k16.row.col.f32.bf16.bf16.f32 "
        "{%0,%1,%2,%3}, {%4,%5,%6,%7}, {%8,%9}, {%0,%1,%2,%3};"
        : "+f"(c[0]), "+f"(c[1]), "+f"(c[2]), "+f"(c[3])
        : "r"(a[0]), "r"(a[1]), "r"(a[2]), "r"(a[3]), "r"(b[0]), "r"(b[1]));
}

__device__ __forceinline__ void load_stage(const __nv_bfloat16* __restrict__ A,
                                           const __nv_bfloat16* __restrict__ B,
                                           int bm, int bn, int kt,
                                           uint32_t sA, uint32_t sB, int tid) {
    int r = tid & 127;
    const char* g;
    uint32_t base;
    if (tid < 128) {
        g = (const char*)(A + (size_t)(bm + r) * D_IN + kt * BK);
        base = sA + r * 128;
    } else {
        g = (const char*)(B + (size_t)(bn + r) * D_IN + kt * BK);
        base = sB + r * 128;
    }
    uint32_t xw = (r & 7) << 4;
#pragma unroll
    for (int j = 0; j < 8; j++) cp16(base + ((j * 16) ^ xw), g + j * 16);
}

__global__ __launch_bounds__(256, 2) void sae_gemm_mma(
    const __nv_bfloat16* __restrict__ A,
    const __nv_bfloat16* __restrict__ B,
    __nv_bfloat16* __restrict__ zb) {
    extern __shared__ char smem[];
    uint32_t sb = smem_to_u32(smem);
    uint32_t sA[NSTAGE], sB[NSTAGE];
#pragma unroll
    for (int s = 0; s < NSTAGE; s++) {
        sA[s] = sb + s * STAGE_BYTES;
        sB[s] = sA[s] + TILE_BYTES;
    }

    int tid = threadIdx.x, wid = tid >> 5, lane = tid & 31;
    int wm = wid >> 2, wn = wid & 3;
    int bm = blockIdx.y * BM, bn = blockIdx.x * BN;

    float acc[4][4][4];
#pragma unroll
    for (int mi = 0; mi < 4; mi++)
#pragma unroll
        for (int ni = 0; ni < 4; ni++)
#pragma unroll
            for (int q = 0; q < 4; q++) acc[mi][ni][q] = 0.0f;

    // prologue: stages 0 and 1 in flight
    load_stage(A, B, bm, bn, 0, sA[0], sB[0], tid); CP_COMMIT();
    load_stage(A, B, bm, bn, 1, sA[1], sB[1], tid); CP_COMMIT();

    for (int kt = 0; kt < NKT; kt++) {
        if (kt == NKT - 1) { CP_WAIT(0); } else { CP_WAIT(1); }
        __syncthreads();   // single barrier per iteration:
                           // guarantees stage kt is loaded AND all warps have
                           // finished compute(kt-1), so stage (kt+2)%3
                           // (== (kt-1)%3) is free to overwrite below.
        int cur = kt % NSTAGE;
        uint32_t cA = sA[cur], cB = sB[cur];

        // issue loads for stage kt+2 FIRST so they overlap this tile's math
        if (kt + 2 < NKT) {
            int nxt = (kt + 2) % NSTAGE;
            load_stage(A, B, bm, bn, kt + 2, sA[nxt], sB[nxt], tid);
            CP_COMMIT();
        }

#pragma unroll
        for (int ks = 0; ks < 4; ks++) {
            uint32_t af[4][4], bf[4][2];
#pragma unroll
            for (int mi = 0; mi < 4; mi++) {
                int r = wm * 64 + mi * 16 + (lane & 15);
                uint32_t off = (uint32_t)(ks * 32 + ((lane >> 4) * 16));
                ldm_x4(af[mi], cA + r * 128 + (off ^ ((r & 7) << 4)));
            }
#pragma unroll
            for (int ni = 0; ni < 4; ni++) {
                int n = wn * 32 + ni * 8 + (lane & 7);
                uint32_t off = (uint32_t)(ks * 32 + (((lane >> 3) & 1) * 16));
                ldm_x2(bf[ni], cB + n * 128 + (off ^ ((n & 7) << 4)));
            }
#pragma unroll
            for (int mi = 0; mi < 4; mi++)
#pragma unroll
                for (int ni = 0; ni < 4; ni++)
                    mma16816(acc[mi][ni], af[mi], bf[ni]);
        }
    }

    int row_base = bm + wm * 64 + (lane >> 2);
    int col_base = bn + wn * 32 + (lane & 3) * 2;
#pragma unroll
    for (int mi = 0; mi < 4; mi++) {
#pragma unroll
        for (int ni = 0; ni < 4; ni++) {
            int col = col_base + ni * 8;
            float* c = acc[mi][ni];
            __nv_bfloat162 v01 = __floats2bfloat162_rn(fmaxf(c[0], 0.f), fmaxf(c[1], 0.f));
            __nv_bfloat162 v23 = __floats2bfloat162_rn(fmaxf(c[2], 0.f), fmaxf(c[3], 0.f));
            int r0 = row_base + mi * 16;
            *reinterpret_cast<__nv_bfloat162*>(zb + (size_t)r0 * D_LAT + col) = v01;
            *reinterpret_cast<__nv_bfloat162*>(zb + (size_t)(r0 + 8) * D_LAT + col) = v23;
        }
    }
}

// ---------------------------------------------------------------------------
// K2: per row — approx top-96 candidates (16-bit radix on bf16 bits),
//     exact fp32 recompute with sequential k-order (reference-matching
//     rounding), exact top-32 (idx tie-break), z write + fused decode.
//     UNCHANGED from R8 (isolates the GEMM delta).
// ---------------------------------------------------------------------------
#define NCAND_T 96
#define CAND_CAP 256

__global__ __launch_bounds__(256) void sae_topk_exact(
    const __nv_bfloat16* __restrict__ zb,
    const float* __restrict__ x, const float* __restrict__ W_enc,
    const float* __restrict__ WdT,
    float* __restrict__ zout, float* __restrict__ xhat) {
    __shared__ unsigned short row16[D_LAT];
    __shared__ float xrow[D_IN];
    __shared__ int hist[256];
    __shared__ int s_pos, s_ncand, s_prefix, s_rem, s_nsel;
    __shared__ int   cidx[CAND_CAP];
    __shared__ float cval[CAND_CAP];
    __shared__ int   sel_idx[K_TOP];
    __shared__ float sel_val[K_TOP];

    int b = blockIdx.x, tid = threadIdx.x;
    int wid = tid >> 5, lane = tid & 31;

    const uint4* src = reinterpret_cast<const uint4*>(zb + (size_t)b * D_LAT);
    for (int i = tid; i < D_LAT / 8; i += 256)
        reinterpret_cast<uint4*>(row16)[i] = src[i];
    for (int i = tid; i < D_IN; i += 256) xrow[i] = x[(size_t)b * D_IN + i];
    if (tid == 0) { s_pos = 0; s_ncand = 0; }
    if (tid < K_TOP) { sel_val[tid] = 0.0f; sel_idx[tid] = 0; }
    hist[tid] = 0;
    __syncthreads();

    int cnt = 0;
    for (int j = tid; j < D_LAT; j += 256) {
        unsigned u = row16[j];
        if (u && !(u & 0x8000)) { cnt++; atomicAdd(&hist[u >> 8], 1); }
    }
    atomicAdd(&s_pos, cnt);
    __syncthreads();

    unsigned T16 = 0;
    if (s_pos >= NCAND_T) {
        if (tid == 0) {
            int cum = 0, d = 255;
            for (; d >= 0; d--) { int h = hist[d]; if (cum + h >= NCAND_T) break; cum += h; }
            s_prefix = d; s_rem = NCAND_T - cum;
        }
        __syncthreads();
        int pfx = s_prefix;
        hist[tid] = 0;
        __syncthreads();
        for (int j = tid; j < D_LAT; j += 256) {
            unsigned u = row16[j];
            if (u && !(u & 0x8000) && (int)(u >> 8) == pfx) atomicAdd(&hist[u & 255], 1);
        }
        __syncthreads();
        if (tid == 0) {
            int cum = 0, d = 255, rem = s_rem;
            for (; d >= 0; d--) { int h = hist[d]; if (cum + h >= rem) break; cum += h; }
            s_prefix = (pfx << 8) | d;
        }
        __syncthreads();
        T16 = (unsigned)s_prefix;
    } else {
        __syncthreads();
    }

    for (int j = tid; j < D_LAT; j += 256) {
        unsigned u = row16[j];
        if (u && !(u & 0x8000) && u >= T16) {
            int p = atomicAdd(&s_ncand, 1);
            if (p < CAND_CAP) cidx[p] = j;
        }
    }
    __syncthreads();
    int ncand = min(s_ncand, CAND_CAP);

    if (tid < ncand) {
        const float* wr = W_enc + (size_t)cidx[tid] * D_IN;
        float acc = 0.0f;
#pragma unroll 8
        for (int t = 0; t < D_IN; t++) acc = fmaf(xrow[t], wr[t], acc);
        cval[tid] = fmaxf(acc, 0.0f);
    }
    if (tid == 0) s_nsel = min(K_TOP, ncand);
    __syncthreads();

    if (wid == 0) {
        int nsel = s_nsel;
        for (int it = 0; it < nsel; it++) {
            float bv = -1.0f; int bi = 0x7FFFFFFF;
            for (int i = lane; i < ncand; i += 32) {
                float v = cval[i]; int ix = cidx[i];
                if (v > bv || (v == bv && ix < bi)) { bv = v; bi = ix; }
            }
#pragma unroll
            for (int o = 16; o; o >>= 1) {
                float ov = __shfl_xor_sync(0xFFFFFFFF, bv, o);
                int   oi = __shfl_xor_sync(0xFFFFFFFF, bi, o);
                if (ov > bv || (ov == bv && oi < bi)) { bv = ov; bi = oi; }
            }
            if (lane == 0) { sel_val[it] = bv; sel_idx[it] = bi; }
            int win = __shfl_sync(0xFFFFFFFF, bi, 0);
            for (int i = lane; i < ncand; i += 32)
                if (cidx[i] == win) cval[i] = -2.0f;
            __syncwarp();
        }
    }
    __syncthreads();

    float* zr = zout + (size_t)b * D_LAT;
    float4 z4 = make_float4(0.f, 0.f, 0.f, 0.f);
    for (int i = tid; i < D_LAT / 4; i += 256)
        reinterpret_cast<float4*>(zr)[i] = z4;
    __syncthreads();
    if (tid < K_TOP && sel_val[tid] > 0.0f) zr[sel_idx[tid]] = sel_val[tid];

    for (int d = tid; d < D_IN; d += 256) {
        float acc = 0.0f;
#pragma unroll
        for (int i = 0; i < K_TOP; i++)
            acc = fmaf(sel_val[i], WdT[(size_t)sel_idx[i] * D_IN + d], acc);
        xhat[(size_t)b * D_IN + d] = acc;
    }
}

// ---------------------------------------------------------------------------
// Launch
// ---------------------------------------------------------------------------
extern "C" void kernel_launch(void* const* d_in, const int* in_sizes, int n_in,
                              void* d_out, int out_size) {
    const float* x     = (const float*)d_in[0];
    const float* W_enc = (const float*)d_in[1];
    const float* W_dec = (const float*)d_in[2];
    (void)in_sizes; (void)n_in; (void)out_size;

    float* out = (float*)d_out;
    const size_t xhat_elems = (size_t)B_ROWS * D_IN;
    float* xhat = out;
    float* zout = out + xhat_elems;

    __nv_bfloat16 *xb, *web, *zbp; float* WdT;
    cudaGetSymbolAddress((void**)&xb,  g_xb);
    cudaGetSymbolAddress((void**)&web, g_web);
    cudaGetSymbolAddress((void**)&zbp, g_zb);
    cudaGetSymbolAddress((void**)&WdT, g_WdT);

    {
        int n4 = (B_ROWS * D_IN) / 4;
        sae_cvt_bf16<<<(n4 + 255) / 256, 256>>>(x, xb, n4);
        n4 = (D_LAT * D_IN) / 4;
        sae_cvt_bf16<<<(n4 + 255) / 256, 256>>>(W_enc, web, n4);
        dim3 tg(D_LAT / 32, D_IN / 32), tb(32, 8);
        sae_transpose_wdec<<<tg, tb>>>(W_dec, WdT);
    }

    cudaFuncSetAttribute(sae_gemm_mma,
                         cudaFuncAttributeMaxDynamicSharedMemorySize, GEMM_SMEM);
    dim3 gg(D_LAT / BN, B_ROWS / BM);
    sae_gemm_mma<<<gg, 256, GEMM_SMEM>>>(xb, web, zbp);

    sae_topk_exact<<<B_ROWS, 256>>>(zbp, x, W_enc, WdT, zout, xhat);
}

// round 10
// speedup vs baseline: 1.3536x; 1.0158x over previous
#include <cuda_runtime.h>
#include <cuda_bf16.h>
#include <cstdint>

#define B_ROWS   8192
#define D_IN     768
#define D_LAT    16384
#define K_TOP    32

// ---------------------------------------------------------------------------
// Helpers
// ---------------------------------------------------------------------------
__device__ __forceinline__ uint32_t smem_to_u32(const void* p) {
    uint32_t a;
    asm("{ .reg .u64 t; cvta.to.shared.u64 t, %1; cvt.u32.u64 %0, t; }"
        : "=r"(a) : "l"(p));
    return a;
}
__device__ __forceinline__ void cp16(uint32_t dst, const void* src) {
    asm volatile("cp.async.cg.shared.global [%0], [%1], 16;" :: "r"(dst), "l"(src));
}
#define CP_COMMIT() asm volatile("cp.async.commit_group;" ::: "memory")
#define CP_WAIT(n)  asm volatile("cp.async.wait_group %0;" :: "n"(n) : "memory")

// ---------------------------------------------------------------------------
// Device scratch
// ---------------------------------------------------------------------------
__device__ __nv_bfloat16 g_xb[(size_t)B_ROWS * D_IN];
__device__ __nv_bfloat16 g_web[(size_t)D_LAT * D_IN];
__device__ __nv_bfloat16 g_zb[(size_t)B_ROWS * D_LAT];
__device__ float         g_WdT[(size_t)D_LAT * D_IN];

// ---------------------------------------------------------------------------
// K0a: fp32 -> bf16 convert
// ---------------------------------------------------------------------------
__global__ void sae_cvt_bf16(const float* __restrict__ in,
                             __nv_bfloat16* __restrict__ out, int n4) {
    for (int i = blockIdx.x * blockDim.x + threadIdx.x; i < n4;
         i += gridDim.x * blockDim.x) {
        float4 v = reinterpret_cast<const float4*>(in)[i];
        __nv_bfloat162* o = reinterpret_cast<__nv_bfloat162*>(out) + 2 * (size_t)i;
        o[0] = __floats2bfloat162_rn(v.x, v.y);
        o[1] = __floats2bfloat162_rn(v.z, v.w);
    }
}

// ---------------------------------------------------------------------------
// K0b: transpose W_dec [768, 16384] -> WdT [16384, 768]
// ---------------------------------------------------------------------------
__global__ void sae_transpose_wdec(const float* __restrict__ in,
                                   float* __restrict__ out) {
    __shared__ float tile[32][33];
    int x = blockIdx.x * 32 + threadIdx.x;
    int y = blockIdx.y * 32 + threadIdx.y;
#pragma unroll
    for (int j = 0; j < 32; j += 8)
        tile[threadIdx.y + j][threadIdx.x] = in[(size_t)(y + j) * D_LAT + x];
    __syncthreads();
    int xo = blockIdx.y * 32 + threadIdx.x;
    int yo = blockIdx.x * 32 + threadIdx.y;
#pragma unroll
    for (int j = 0; j < 32; j += 8)
        out[(size_t)(yo + j) * D_IN + xo] = tile[threadIdx.x][threadIdx.y + j];
}

// ---------------------------------------------------------------------------
// K1: mma.sync bf16 GEMM.  zb = relu(x @ W_enc^T) (bf16 out).
//     CTA tile 128x128, 4 warps (2x2), WARP TILE 64x64,
//     3-stage cp.async, register-fragment double buffering.
//     Per ks: 8 ldmatrix.x4 feed 32 HMMA (was 24 LDSM : 16 HMMA).
// ---------------------------------------------------------------------------
#define BM 128
#define BN 128
#define BK 64
#define NKT (D_IN / BK)                   // 12
#define TILE_BYTES (128 * 128)            // 16 KB per operand tile
#define NSTAGE 3
#define STAGE_BYTES (2 * TILE_BYTES)      // 32 KB (A + B)
#define GEMM_SMEM (NSTAGE * STAGE_BYTES)  // 96 KB

__device__ __forceinline__ void ldm_x4(uint32_t* r, uint32_t addr) {
    asm volatile("ldmatrix.sync.aligned.m8n8.x4.shared.b16 {%0,%1,%2,%3}, [%4];"
                 : "=r"(r[0]), "=r"(r[1]), "=r"(r[2]), "=r"(r[3]) : "r"(addr));
}
__device__ __forceinline__ void mma16816(float* c, const uint32_t* a,
                                         const uint32_t* b) {
    asm volatile(
        "mma.sync.aligned.m16n8k16.row.col.f32.bf16.bf16.f32 "
        "{%0,%1,%2,%3}, {%4,%5,%6,%7}, {%8,%9}, {%0,%1,%2,%3};"
        : "+f"(c[0]), "+f"(c[1]), "+f"(c[2]), "+f"(c[3])
        : "r"(a[0]), "r"(a[1]), "r"(a[2]), "r"(a[3]), "r"(b[0]), "r"(b[1]));
}

__device__ __forceinline__ void load_stage(const __nv_bfloat16* __restrict__ A,
                                           const __nv_bfloat16* __restrict__ B,
                                           int bm, int bn, int kt,
                                           uint32_t sA, uint32_t sB, int tid) {
    int r = tid;                         // 0..127: one A row + one B row each
    uint32_t xw = (r & 7) << 4;
    const char* ga = (const char*)(A + (size_t)(bm + r) * D_IN + kt * BK);
    uint32_t ba = sA + r * 128;
#pragma unroll
    for (int j = 0; j < 8; j++) cp16(ba + ((j * 16) ^ xw), ga + j * 16);
    const char* gb = (const char*)(B + (size_t)(bn + r) * D_IN + kt * BK);
    uint32_t bb = sB + r * 128;
#pragma unroll
    for (int j = 0; j < 8; j++) cp16(bb + ((j * 16) ^ xw), gb + j * 16);
}

// A fragments: 4 m-tiles (m16), one ldm_x4 each
__device__ __forceinline__ void load_a_frags(uint32_t af[4][4], uint32_t cA,
                                             int wm, int lane, int ks) {
#pragma unroll
    for (int mi = 0; mi < 4; mi++) {
        int r = wm * 64 + mi * 16 + (lane & 15);
        uint32_t off = (uint32_t)(ks * 32 + ((lane >> 4) * 16));
        ldm_x4(af[mi], cA + r * 128 + (off ^ ((r & 7) << 4)));
    }
}
// B fragments: 8 n-tiles (n8) as 4 paired ldm_x4
__device__ __forceinline__ void load_b_frags(uint32_t bf[8][2], uint32_t cB,
                                             int wn, int lane, int ks) {
#pragma unroll
    for (int np = 0; np < 4; np++) {
        int n = wn * 64 + np * 16 + (lane & 7) + ((lane >> 4) << 3);
        uint32_t off = (uint32_t)(ks * 32 + (((lane >> 3) & 1) * 16));
        uint32_t r4[4];
        ldm_x4(r4, cB + n * 128 + (off ^ ((n & 7) << 4)));
        bf[2 * np][0] = r4[0];     bf[2 * np][1] = r4[1];
        bf[2 * np + 1][0] = r4[2]; bf[2 * np + 1][1] = r4[3];
    }
}

__global__ __launch_bounds__(128, 2) void sae_gemm_mma(
    const __nv_bfloat16* __restrict__ A,
    const __nv_bfloat16* __restrict__ B,
    __nv_bfloat16* __restrict__ zb) {
    extern __shared__ char smem[];
    uint32_t sb = smem_to_u32(smem);
    uint32_t sA[NSTAGE], sB[NSTAGE];
#pragma unroll
    for (int s = 0; s < NSTAGE; s++) {
        sA[s] = sb + s * STAGE_BYTES;
        sB[s] = sA[s] + TILE_BYTES;
    }

    int tid = threadIdx.x, wid = tid >> 5, lane = tid & 31;
    int wm = wid >> 1, wn = wid & 1;           // 2x2 warp grid, 64x64 tiles
    int bm = blockIdx.y * BM, bn = blockIdx.x * BN;

    float acc[4][8][4];
#pragma unroll
    for (int mi = 0; mi < 4; mi++)
#pragma unroll
        for (int ni = 0; ni < 8; ni++)
#pragma unroll
            for (int q = 0; q < 4; q++) acc[mi][ni][q] = 0.0f;

    load_stage(A, B, bm, bn, 0, sA[0], sB[0], tid); CP_COMMIT();
    load_stage(A, B, bm, bn, 1, sA[1], sB[1], tid); CP_COMMIT();

    uint32_t af[2][4][4], bf[2][8][2];

    for (int kt = 0; kt < NKT; kt++) {
        if (kt == NKT - 1) { CP_WAIT(0); } else { CP_WAIT(1); }
        __syncthreads();   // stage kt ready; all warps done with kt-1's tiles
        int cur = kt % NSTAGE;
        uint32_t cA = sA[cur], cB = sB[cur];

        // async loads for stage kt+2 overlap this tile's math
        if (kt + 2 < NKT) {
            int nxt = (kt + 2) % NSTAGE;
            load_stage(A, B, bm, bn, kt + 2, sA[nxt], sB[nxt], tid);
            CP_COMMIT();
        }

        // software-pipelined fragments: prefetch ks+1 while computing ks
        load_a_frags(af[0], cA, wm, lane, 0);
        load_b_frags(bf[0], cB, wn, lane, 0);
#pragma unroll
        for (int ks = 0; ks < 4; ks++) {
            int c = ks & 1, n = c ^ 1;
            if (ks < 3) {
                load_a_frags(af[n], cA, wm, lane, ks + 1);
                load_b_frags(bf[n], cB, wn, lane, ks + 1);
            }
#pragma unroll
            for (int mi = 0; mi < 4; mi++)
#pragma unroll
                for (int ni = 0; ni < 8; ni++)
                    mma16816(acc[mi][ni], af[c][mi], bf[c][ni]);
        }
    }

    // Epilogue: ReLU + bf16 store from fragments
    int row_base = bm + wm * 64 + (lane >> 2);
    int col_base = bn + wn * 64 + (lane & 3) * 2;
#pragma unroll
    for (int mi = 0; mi < 4; mi++) {
#pragma unroll
        for (int ni = 0; ni < 8; ni++) {
            int col = col_base + ni * 8;
            float* c = acc[mi][ni];
            __nv_bfloat162 v01 = __floats2bfloat162_rn(fmaxf(c[0], 0.f), fmaxf(c[1], 0.f));
            __nv_bfloat162 v23 = __floats2bfloat162_rn(fmaxf(c[2], 0.f), fmaxf(c[3], 0.f));
            int r0 = row_base + mi * 16;
            *reinterpret_cast<__nv_bfloat162*>(zb + (size_t)r0 * D_LAT + col) = v01;
            *reinterpret_cast<__nv_bfloat162*>(zb + (size_t)(r0 + 8) * D_LAT + col) = v23;
        }
    }
}

// ---------------------------------------------------------------------------
// K2: per row — approx top-96 candidates (16-bit radix on bf16 bits),
//     exact fp32 recompute with sequential k-order, exact top-32,
//     z write + fused decode.  UNCHANGED (isolates the GEMM delta).
// ---------------------------------------------------------------------------
#define NCAND_T 96
#define CAND_CAP 256

__global__ __launch_bounds__(256) void sae_topk_exact(
    const __nv_bfloat16* __restrict__ zb,
    const float* __restrict__ x, const float* __restrict__ W_enc,
    const float* __restrict__ WdT,
    float* __restrict__ zout, float* __restrict__ xhat) {
    __shared__ unsigned short row16[D_LAT];
    __shared__ float xrow[D_IN];
    __shared__ int hist[256];
    __shared__ int s_pos, s_ncand, s_prefix, s_rem, s_nsel;
    __shared__ int   cidx[CAND_CAP];
    __shared__ float cval[CAND_CAP];
    __shared__ int   sel_idx[K_TOP];
    __shared__ float sel_val[K_TOP];

    int b = blockIdx.x, tid = threadIdx.x;
    int wid = tid >> 5, lane = tid & 31;

    const uint4* src = reinterpret_cast<const uint4*>(zb + (size_t)b * D_LAT);
    for (int i = tid; i < D_LAT / 8; i += 256)
        reinterpret_cast<uint4*>(row16)[i] = src[i];
    for (int i = tid; i < D_IN; i += 256) xrow[i] = x[(size_t)b * D_IN + i];
    if (tid == 0) { s_pos = 0; s_ncand = 0; }
    if (tid < K_TOP) { sel_val[tid] = 0.0f; sel_idx[tid] = 0; }
    hist[tid] = 0;
    __syncthreads();

    int cnt = 0;
    for (int j = tid; j < D_LAT; j += 256) {
        unsigned u = row16[j];
        if (u && !(u & 0x8000)) { cnt++; atomicAdd(&hist[u >> 8], 1); }
    }
    atomicAdd(&s_pos, cnt);
    __syncthreads();

    unsigned T16 = 0;
    if (s_pos >= NCAND_T) {
        if (tid == 0) {
            int cum = 0, d = 255;
            for (; d >= 0; d--) { int h = hist[d]; if (cum + h >= NCAND_T) break; cum += h; }
            s_prefix = d; s_rem = NCAND_T - cum;
        }
        __syncthreads();
        int pfx = s_prefix;
        hist[tid] = 0;
        __syncthreads();
        for (int j = tid; j < D_LAT; j += 256) {
            unsigned u = row16[j];
            if (u && !(u & 0x8000) && (int)(u >> 8) == pfx) atomicAdd(&hist[u & 255], 1);
        }
        __syncthreads();
        if (tid == 0) {
            int cum = 0, d = 255, rem = s_rem;
            for (; d >= 0; d--) { int h = hist[d]; if (cum + h >= rem) break; cum += h; }
            s_prefix = (pfx << 8) | d;
        }
        __syncthreads();
        T16 = (unsigned)s_prefix;
    } else {
        __syncthreads();
    }

    for (int j = tid; j < D_LAT; j += 256) {
        unsigned u = row16[j];
        if (u && !(u & 0x8000) && u >= T16) {
            int p = atomicAdd(&s_ncand, 1);
            if (p < CAND_CAP) cidx[p] = j;
        }
    }
    __syncthreads();
    int ncand = min(s_ncand, CAND_CAP);

    if (tid < ncand) {
        const float* wr = W_enc + (size_t)cidx[tid] * D_IN;
        float acc = 0.0f;
#pragma unroll 8
        for (int t = 0; t < D_IN; t++) acc = fmaf(xrow[t], wr[t], acc);
        cval[tid] = fmaxf(acc, 0.0f);
    }
    if (tid == 0) s_nsel = min(K_TOP, ncand);
    __syncthreads();

    if (wid == 0) {
        int nsel = s_nsel;
        for (int it = 0; it < nsel; it++) {
            float bv = -1.0f; int bi = 0x7FFFFFFF;
            for (int i = lane; i < ncand; i += 32) {
                float v = cval[i]; int ix = cidx[i];
                if (v > bv || (v == bv && ix < bi)) { bv = v; bi = ix; }
            }
#pragma unroll
            for (int o = 16; o; o >>= 1) {
                float ov = __shfl_xor_sync(0xFFFFFFFF, bv, o);
                int   oi = __shfl_xor_sync(0xFFFFFFFF, bi, o);
                if (ov > bv || (ov == bv && oi < bi)) { bv = ov; bi = oi; }
            }
            if (lane == 0) { sel_val[it] = bv; sel_idx[it] = bi; }
            int win = __shfl_sync(0xFFFFFFFF, bi, 0);
            for (int i = lane; i < ncand; i += 32)
                if (cidx[i] == win) cval[i] = -2.0f;
            __syncwarp();
        }
    }
    __syncthreads();

    float* zr = zout + (size_t)b * D_LAT;
    float4 z4 = make_float4(0.f, 0.f, 0.f, 0.f);
    for (int i = tid; i < D_LAT / 4; i += 256)
        reinterpret_cast<float4*>(zr)[i] = z4;
    __syncthreads();
    if (tid < K_TOP && sel_val[tid] > 0.0f) zr[sel_idx[tid]] = sel_val[tid];

    for (int d = tid; d < D_IN; d += 256) {
        float acc = 0.0f;
#pragma unroll
        for (int i = 0; i < K_TOP; i++)
            acc = fmaf(sel_val[i], WdT[(size_t)sel_idx[i] * D_IN + d], acc);
        xhat[(size_t)b * D_IN + d] = acc;
    }
}

// ---------------------------------------------------------------------------
// Launch
// ---------------------------------------------------------------------------
extern "C" void kernel_launch(void* const* d_in, const int* in_sizes, int n_in,
                              void* d_out, int out_size) {
    const float* x     = (const float*)d_in[0];
    const float* W_enc = (const float*)d_in[1];
    const float* W_dec = (const float*)d_in[2];
    (void)in_sizes; (void)n_in; (void)out_size;

    float* out = (float*)d_out;
    const size_t xhat_elems = (size_t)B_ROWS * D_IN;
    float* xhat = out;
    float* zout = out + xhat_elems;

    __nv_bfloat16 *xb, *web, *zbp; float* WdT;
    cudaGetSymbolAddress((void**)&xb,  g_xb);
    cudaGetSymbolAddress((void**)&web, g_web);
    cudaGetSymbolAddress((void**)&zbp, g_zb);
    cudaGetSymbolAddress((void**)&WdT, g_WdT);

    {
        int n4 = (B_ROWS * D_IN) / 4;
        sae_cvt_bf16<<<(n4 + 255) / 256, 256>>>(x, xb, n4);
        n4 = (D_LAT * D_IN) / 4;
        sae_cvt_bf16<<<(n4 + 255) / 256, 256>>>(W_enc, web, n4);
        dim3 tg(D_LAT / 32, D_IN / 32), tb(32, 8);
        sae_transpose_wdec<<<tg, tb>>>(W_dec, WdT);
    }

    cudaFuncSetAttribute(sae_gemm_mma,
                         cudaFuncAttributeMaxDynamicSharedMemorySize, GEMM_SMEM);
    dim3 gg(D_LAT / BN, B_ROWS / BM);
    sae_gemm_mma<<<gg, 128, GEMM_SMEM>>>(xb, web, zbp);

    sae_topk_exact<<<B_ROWS, 256>>>(zbp, x, W_enc, WdT, zout, xhat);
}

// round 12
// speedup vs baseline: 2.0769x; 1.5343x over previous
#include <cuda_runtime.h>
#include <cuda_bf16.h>
#include <cstdint>

#define B_ROWS   8192
#define D_IN     768
#define D_LAT    16384
#define K_TOP    32

// ---------------------------------------------------------------------------
// Helpers
// ---------------------------------------------------------------------------
__device__ __forceinline__ uint32_t smem_to_u32(const void* p) {
    uint32_t a;
    asm("{ .reg .u64 t; cvta.to.shared.u64 t, %1; cvt.u32.u64 %0, t; }"
        : "=r"(a) : "l"(p));
    return a;
}
__device__ __forceinline__ void cp16(uint32_t dst, const void* src) {
    asm volatile("cp.async.cg.shared.global [%0], [%1], 16;" :: "r"(dst), "l"(src));
}
#define CP_COMMIT() asm volatile("cp.async.commit_group;" ::: "memory")
#define CP_WAIT(n)  asm volatile("cp.async.wait_group %0;" :: "n"(n) : "memory")

// ---------------------------------------------------------------------------
// Device scratch
// ---------------------------------------------------------------------------
__device__ __nv_bfloat16 g_xb[(size_t)B_ROWS * D_IN];
__device__ __nv_bfloat16 g_web[(size_t)D_LAT * D_IN];
__device__ __nv_bfloat16 g_zb[(size_t)B_ROWS * D_LAT];
__device__ float         g_WdT[(size_t)D_LAT * D_IN];

// ---------------------------------------------------------------------------
// K0a: fp32 -> bf16 convert
// ---------------------------------------------------------------------------
__global__ void sae_cvt_bf16(const float* __restrict__ in,
                             __nv_bfloat16* __restrict__ out, int n4) {
    for (int i = blockIdx.x * blockDim.x + threadIdx.x; i < n4;
         i += gridDim.x * blockDim.x) {
        float4 v = reinterpret_cast<const float4*>(in)[i];
        __nv_bfloat162* o = reinterpret_cast<__nv_bfloat162*>(out) + 2 * (size_t)i;
        o[0] = __floats2bfloat162_rn(v.x, v.y);
        o[1] = __floats2bfloat162_rn(v.z, v.w);
    }
}

// ---------------------------------------------------------------------------
// K0b: transpose W_dec [768, 16384] -> WdT [16384, 768]
// ---------------------------------------------------------------------------
__global__ void sae_transpose_wdec(const float* __restrict__ in,
                                   float* __restrict__ out) {
    __shared__ float tile[32][33];
    int x = blockIdx.x * 32 + threadIdx.x;
    int y = blockIdx.y * 32 + threadIdx.y;
#pragma unroll
    for (int j = 0; j < 32; j += 8)
        tile[threadIdx.y + j][threadIdx.x] = in[(size_t)(y + j) * D_LAT + x];
    __syncthreads();
    int xo = blockIdx.y * 32 + threadIdx.x;
    int yo = blockIdx.x * 32 + threadIdx.y;
#pragma unroll
    for (int j = 0; j < 32; j += 8)
        out[(size_t)(yo + j) * D_IN + xo] = tile[threadIdx.x][threadIdx.y + j];
}

// ---------------------------------------------------------------------------
// K1: mma.sync bf16 GEMM (unchanged from R10).
// ---------------------------------------------------------------------------
#define BM 128
#define BN 128
#define BK 64
#define NKT (D_IN / BK)
#define TILE_BYTES (128 * 128)
#define NSTAGE 3
#define STAGE_BYTES (2 * TILE_BYTES)
#define GEMM_SMEM (NSTAGE * STAGE_BYTES)

__device__ __forceinline__ void ldm_x4(uint32_t* r, uint32_t addr) {
    asm volatile("ldmatrix.sync.aligned.m8n8.x4.shared.b16 {%0,%1,%2,%3}, [%4];"
                 : "=r"(r[0]), "=r"(r[1]), "=r"(r[2]), "=r"(r[3]) : "r"(addr));
}
__device__ __forceinline__ void mma16816(float* c, const uint32_t* a,
                                         const uint32_t* b) {
    asm volatile(
        "mma.sync.aligned.m16n8k16.row.col.f32.bf16.bf16.f32 "
        "{%0,%1,%2,%3}, {%4,%5,%6,%7}, {%8,%9}, {%0,%1,%2,%3};"
        : "+f"(c[0]), "+f"(c[1]), "+f"(c[2]), "+f"(c[3])
        : "r"(a[0]), "r"(a[1]), "r"(a[2]), "r"(a[3]), "r"(b[0]), "r"(b[1]));
}

__device__ __forceinline__ void load_stage(const __nv_bfloat16* __restrict__ A,
                                           const __nv_bfloat16* __restrict__ B,
                                           int bm, int bn, int kt,
                                           uint32_t sA, uint32_t sB, int tid) {
    int r = tid;
    uint32_t xw = (r & 7) << 4;
    const char* ga = (const char*)(A + (size_t)(bm + r) * D_IN + kt * BK);
    uint32_t ba = sA + r * 128;
#pragma unroll
    for (int j = 0; j < 8; j++) cp16(ba + ((j * 16) ^ xw), ga + j * 16);
    const char* gb = (const char*)(B + (size_t)(bn + r) * D_IN + kt * BK);
    uint32_t bb = sB + r * 128;
#pragma unroll
    for (int j = 0; j < 8; j++) cp16(bb + ((j * 16) ^ xw), gb + j * 16);
}

__device__ __forceinline__ void load_a_frags(uint32_t af[4][4], uint32_t cA,
                                             int wm, int lane, int ks) {
#pragma unroll
    for (int mi = 0; mi < 4; mi++) {
        int r = wm * 64 + mi * 16 + (lane & 15);
        uint32_t off = (uint32_t)(ks * 32 + ((lane >> 4) * 16));
        ldm_x4(af[mi], cA + r * 128 + (off ^ ((r & 7) << 4)));
    }
}
__device__ __forceinline__ void load_b_frags(uint32_t bf[8][2], uint32_t cB,
                                             int wn, int lane, int ks) {
#pragma unroll
    for (int np = 0; np < 4; np++) {
        int n = wn * 64 + np * 16 + (lane & 7) + ((lane >> 4) << 3);
        uint32_t off = (uint32_t)(ks * 32 + (((lane >> 3) & 1) * 16));
        uint32_t r4[4];
        ldm_x4(r4, cB + n * 128 + (off ^ ((n & 7) << 4)));
        bf[2 * np][0] = r4[0];     bf[2 * np][1] = r4[1];
        bf[2 * np + 1][0] = r4[2]; bf[2 * np + 1][1] = r4[3];
    }
}

__global__ __launch_bounds__(128, 2) void sae_gemm_mma(
    const __nv_bfloat16* __restrict__ A,
    const __nv_bfloat16* __restrict__ B,
    __nv_bfloat16* __restrict__ zb) {
    extern __shared__ char smem[];
    uint32_t sb = smem_to_u32(smem);
    uint32_t sA[NSTAGE], sB[NSTAGE];
#pragma unroll
    for (int s = 0; s < NSTAGE; s++) {
        sA[s] = sb + s * STAGE_BYTES;
        sB[s] = sA[s] + TILE_BYTES;
    }

    int tid = threadIdx.x, wid = tid >> 5, lane = tid & 31;
    int wm = wid >> 1, wn = wid & 1;
    int bm = blockIdx.y * BM, bn = blockIdx.x * BN;

    float acc[4][8][4];
#pragma unroll
    for (int mi = 0; mi < 4; mi++)
#pragma unroll
        for (int ni = 0; ni < 8; ni++)
#pragma unroll
            for (int q = 0; q < 4; q++) acc[mi][ni][q] = 0.0f;

    load_stage(A, B, bm, bn, 0, sA[0], sB[0], tid); CP_COMMIT();
    load_stage(A, B, bm, bn, 1, sA[1], sB[1], tid); CP_COMMIT();

    uint32_t af[2][4][4], bf[2][8][2];

    for (int kt = 0; kt < NKT; kt++) {
        if (kt == NKT - 1) { CP_WAIT(0); } else { CP_WAIT(1); }
        __syncthreads();
        int cur = kt % NSTAGE;
        uint32_t cA = sA[cur], cB = sB[cur];

        if (kt + 2 < NKT) {
            int nxt = (kt + 2) % NSTAGE;
            load_stage(A, B, bm, bn, kt + 2, sA[nxt], sB[nxt], tid);
            CP_COMMIT();
        }

        load_a_frags(af[0], cA, wm, lane, 0);
        load_b_frags(bf[0], cB, wn, lane, 0);
#pragma unroll
        for (int ks = 0; ks < 4; ks++) {
            int c = ks & 1, n = c ^ 1;
            if (ks < 3) {
                load_a_frags(af[n], cA, wm, lane, ks + 1);
                load_b_frags(bf[n], cB, wn, lane, ks + 1);
            }
#pragma unroll
            for (int mi = 0; mi < 4; mi++)
#pragma unroll
                for (int ni = 0; ni < 8; ni++)
                    mma16816(acc[mi][ni], af[c][mi], bf[c][ni]);
        }
    }

    int row_base = bm + wm * 64 + (lane >> 2);
    int col_base = bn + wn * 64 + (lane & 3) * 2;
#pragma unroll
    for (int mi = 0; mi < 4; mi++) {
#pragma unroll
        for (int ni = 0; ni < 8; ni++) {
            int col = col_base + ni * 8;
            float* c = acc[mi][ni];
            __nv_bfloat162 v01 = __floats2bfloat162_rn(fmaxf(c[0], 0.f), fmaxf(c[1], 0.f));
            __nv_bfloat162 v23 = __floats2bfloat162_rn(fmaxf(c[2], 0.f), fmaxf(c[3], 0.f));
            int r0 = row_base + mi * 16;
            *reinterpret_cast<__nv_bfloat162*>(zb + (size_t)r0 * D_LAT + col) = v01;
            *reinterpret_cast<__nv_bfloat162*>(zb + (size_t)(r0 + 8) * D_LAT + col) = v23;
        }
    }
}

// ---------------------------------------------------------------------------
// K2: per row — approx top-64 candidates, exact fp32 recompute
//     (sequential k-order, FLOAT4 loads -> kills 8x L2 sector amplification),
//     exact top-32, z write + fused decode.
// ---------------------------------------------------------------------------
#define NCAND_T 64
#define CAND_CAP 256

__global__ __launch_bounds__(256) void sae_topk_exact(
    const __nv_bfloat16* __restrict__ zb,
    const float* __restrict__ x, const float* __restrict__ W_enc,
    const float* __restrict__ WdT,
    float* __restrict__ zout, float* __restrict__ xhat) {
    __shared__ unsigned short row16[D_LAT];
    __shared__ __align__(16) float xrow[D_IN];
    __shared__ int hist[256];
    __shared__ int s_pos, s_ncand, s_prefix, s_rem, s_nsel;
    __shared__ int   cidx[CAND_CAP];
    __shared__ float cval[CAND_CAP];
    __shared__ int   sel_idx[K_TOP];
    __shared__ float sel_val[K_TOP];

    int b = blockIdx.x, tid = threadIdx.x;
    int wid = tid >> 5, lane = tid & 31;

    const uint4* src = reinterpret_cast<const uint4*>(zb + (size_t)b * D_LAT);
    for (int i = tid; i < D_LAT / 8; i += 256)
        reinterpret_cast<uint4*>(row16)[i] = src[i];
    for (int i = tid; i < D_IN; i += 256) xrow[i] = x[(size_t)b * D_IN + i];
    if (tid == 0) { s_pos = 0; s_ncand = 0; }
    if (tid < K_TOP) { sel_val[tid] = 0.0f; sel_idx[tid] = 0; }
    hist[tid] = 0;
    __syncthreads();

    int cnt = 0;
    for (int j = tid; j < D_LAT; j += 256) {
        unsigned u = row16[j];
        if (u && !(u & 0x8000)) { cnt++; atomicAdd(&hist[u >> 8], 1); }
    }
    atomicAdd(&s_pos, cnt);
    __syncthreads();

    unsigned T16 = 0;
    if (s_pos >= NCAND_T) {
        if (tid == 0) {
            int cum = 0, d = 255;
            for (; d >= 0; d--) { int h = hist[d]; if (cum + h >= NCAND_T) break; cum += h; }
            s_prefix = d; s_rem = NCAND_T - cum;
        }
        __syncthreads();
        int pfx = s_prefix;
        hist[tid] = 0;
        __syncthreads();
        for (int j = tid; j < D_LAT; j += 256) {
            unsigned u = row16[j];
            if (u && !(u & 0x8000) && (int)(u >> 8) == pfx) atomicAdd(&hist[u & 255], 1);
        }
        __syncthreads();
        if (tid == 0) {
            int cum = 0, d = 255, rem = s_rem;
            for (; d >= 0; d--) { int h = hist[d]; if (cum + h >= rem) break; cum += h; }
            s_prefix = (pfx << 8) | d;
        }
        __syncthreads();
        T16 = (unsigned)s_prefix;
    } else {
        __syncthreads();
    }

    for (int j = tid; j < D_LAT; j += 256) {
        unsigned u = row16[j];
        if (u && !(u & 0x8000) && u >= T16) {
            int p = atomicAdd(&s_ncand, 1);
            if (p < CAND_CAP) cidx[p] = j;
        }
    }
    __syncthreads();
    int ncand = min(s_ncand, CAND_CAP);

    // Exact fp32 recompute: one thread per candidate, single accumulator,
    // SEQUENTIAL k = 0..767 (reference-matching rounding, proven in R8).
    // float4 loads: W_enc rows are 3072B-aligned -> 16B-aligned, so the
    // warp's 32 scattered rows cost 2x sectors instead of 8x.
    if (tid < ncand) {
        const float4* wr = reinterpret_cast<const float4*>(
            W_enc + (size_t)cidx[tid] * D_IN);
        const float4* xr = reinterpret_cast<const float4*>(xrow);
        float acc = 0.0f;
#pragma unroll 4
        for (int t = 0; t < D_IN / 4; t++) {
            float4 w = wr[t];
            float4 xv = xr[t];
            acc = fmaf(xv.x, w.x, acc);
            acc = fmaf(xv.y, w.y, acc);
            acc = fmaf(xv.z, w.z, acc);
            acc = fmaf(xv.w, w.w, acc);
        }
        cval[tid] = fmaxf(acc, 0.0f);
    }
    if (tid == 0) s_nsel = min(K_TOP, ncand);
    __syncthreads();

    if (wid == 0) {
        int nsel = s_nsel;
        for (int it = 0; it < nsel; it++) {
            float bv = -1.0f; int bi = 0x7FFFFFFF;
            for (int i = lane; i < ncand; i += 32) {
                float v = cval[i]; int ix = cidx[i];
                if (v > bv || (v == bv && ix < bi)) { bv = v; bi = ix; }
            }
#pragma unroll
            for (int o = 16; o; o >>= 1) {
                float ov = __shfl_xor_sync(0xFFFFFFFF, bv, o);
                int   oi = __shfl_xor_sync(0xFFFFFFFF, bi, o);
                if (ov > bv || (ov == bv && oi < bi)) { bv = ov; bi = oi; }
            }
            if (lane == 0) { sel_val[it] = bv; sel_idx[it] = bi; }
            int win = __shfl_sync(0xFFFFFFFF, bi, 0);
            for (int i = lane; i < ncand; i += 32)
                if (cidx[i] == win) cval[i] = -2.0f;
            __syncwarp();
        }
    }
    __syncthreads();

    float* zr = zout + (size_t)b * D_LAT;
    float4 z4 = make_float4(0.f, 0.f, 0.f, 0.f);
    for (int i = tid; i < D_LAT / 4; i += 256)
        reinterpret_cast<float4*>(zr)[i] = z4;
    __syncthreads();
    if (tid < K_TOP && sel_val[tid] > 0.0f) zr[sel_idx[tid]] = sel_val[tid];

    for (int d = tid; d < D_IN; d += 256) {
        float acc = 0.0f;
#pragma unroll
        for (int i = 0; i < K_TOP; i++)
            acc = fmaf(sel_val[i], WdT[(size_t)sel_idx[i] * D_IN + d], acc);
        xhat[(size_t)b * D_IN + d] = acc;
    }
}

// ---------------------------------------------------------------------------
// Launch
// ---------------------------------------------------------------------------
extern "C" void kernel_launch(void* const* d_in, const int* in_sizes, int n_in,
                              void* d_out, int out_size) {
    const float* x     = (const float*)d_in[0];
    const float* W_enc = (const float*)d_in[1];
    const float* W_dec = (const float*)d_in[2];
    (void)in_sizes; (void)n_in; (void)out_size;

    float* out = (float*)d_out;
    const size_t xhat_elems = (size_t)B_ROWS * D_IN;
    float* xhat = out;
    float* zout = out + xhat_elems;

    __nv_bfloat16 *xb, *web, *zbp; float* WdT;
    cudaGetSymbolAddress((void**)&xb,  g_xb);
    cudaGetSymbolAddress((void**)&web, g_web);
    cudaGetSymbolAddress((void**)&zbp, g_zb);
    cudaGetSymbolAddress((void**)&WdT, g_WdT);

    {
        int n4 = (B_ROWS * D_IN) / 4;
        sae_cvt_bf16<<<(n4 + 255) / 256, 256>>>(x, xb, n4);
        n4 = (D_LAT * D_IN) / 4;
        sae_cvt_bf16<<<(n4 + 255) / 256, 256>>>(W_enc, web, n4);
        dim3 tg(D_LAT / 32, D_IN / 32), tb(32, 8);
        sae_transpose_wdec<<<tg, tb>>>(W_dec, WdT);
    }

    cudaFuncSetAttribute(sae_gemm_mma,
                         cudaFuncAttributeMaxDynamicSharedMemorySize, GEMM_SMEM);
    dim3 gg(D_LAT / BN, B_ROWS / BM);
    sae_gemm_mma<<<gg, 128, GEMM_SMEM>>>(xb, web, zbp);

    sae_topk_exact<<<B_ROWS, 256>>>(zbp, x, W_enc, WdT, zout, xhat);
}